// round 10
// baseline (speedup 1.0000x reference)
#include <cuda_runtime.h>
#include <cstdint>

// Problem constants
#define B_   2048
#define MND  128
#define D_   512
#define H_   512
#define KF   2048    // GEMM K = 4*512
#define KSEG 512     // K per gemm CTA (split x4)
#define NKH  4

// Scratch (device globals; no allocations allowed)
__device__ float g_X[(size_t)B_ * KF];               // [2048,2048]
__device__ float g_Wbig[(size_t)H_ * KF];            // [512,2048]
__device__ float g_bc[H_];                           // combined bias
__device__ float g_part[NKH][(size_t)B_ * H_];       // K-split partials (16MB)

// ===========================================================================
// Mega-kernel. Roles (0 gemm, 1 means, 2 epi, 3 wc, 4 prep, 5 bc) are chosen
// from blockIdx.x via per-launch interleave patterns so every SM gets a
// balanced DRAM-bound/FMA-bound mix. __launch_bounds__(256,6) caps regs at
// ~40 -> 6 blocks/SM so co-resident means blocks keep chip MLP high.
// ===========================================================================
__global__ void __launch_bounds__(256, 6) mega_kernel(
    const float* __restrict__ img,    const float* __restrict__ txt,
    const float* __restrict__ it,     const float* __restrict__ ii,
    const float* __restrict__ Wl_img, const float* __restrict__ Wl_txt,
    const float* __restrict__ Wr_img, const float* __restrict__ Wr_txt,
    const float* __restrict__ Wuser,  const float* __restrict__ b_user,
    const float* __restrict__ bl_img, const float* __restrict__ bl_txt,
    float* __restrict__ out,
    int pattern, int gemmRow, int meansRow, int epiRow)
{
    __shared__ float As[16][68];
    __shared__ float Bs[16][68];
    __shared__ float red8[8];

    const int tid = threadIdx.x;
    const int bid = blockIdx.x;

    int role, idx;
    switch (pattern) {
    case 0: {   // S0: wc(128) | means(512) | prep(256) | bc(512)
        if (bid < 128)            { role = 3; idx = bid; }
        else { int q = bid - 128;
            if (q < 512)          { role = 1; idx = q; }
            else if (q < 768)     { role = 4; idx = q - 512; }
            else                  { role = 5; idx = q - 768; } }
        break; }
    case 1: {   // S1: means(512) + gemm(256), period 3
        int i = bid % 3, j = bid / 3;
        if (i < 2) { role = 1; idx = 2 * j + i; } else { role = 0; idx = j; }
        break; }
    case 2: {   // S2/S3: means(512) + gemm(256) + epi(256), period 4
        int i = bid & 3, j = bid >> 2;
        if (i < 2)      { role = 1; idx = 2 * j + i; }
        else if (i == 2){ role = 0; idx = j; }
        else            { role = 2; idx = j; }
        break; }
    case 3: {   // S4: gemm(256) + epi(256), period 2
        role = (bid & 1) ? 2 : 0; idx = bid >> 1;
        break; }
    default:    // S5: epi(256)
        role = 2; idx = bid; break;
    }

    // ---------------- GEMM role: g_part[kh] = X[rows,kseg] @ Wbig[:,kseg]^T
    if (role == 0) {
        const int bn  = idx & 7;          // col tile (512/64)
        const int bmq = (idx >> 3) & 7;   // row tile (512/64)
        const int kh  = idx >> 6;         // K segment 0..3
        const int tn = tid & 15, tm = tid >> 4;
        const int ar = tid >> 2, akv = tid & 3;

        const int row0 = gemmRow + bmq * 64;
        const int kb   = kh * KSEG;
        const float* Ap = g_X    + (size_t)(row0 + ar) * KF + kb + akv * 4;
        const float* Bp = g_Wbig + (size_t)(bn * 64 + ar) * KF + kb + akv * 4;

        float acc[4][4] = {};
        for (int k0 = 0; k0 < KSEG; k0 += 16) {
            float4 av = *(const float4*)(Ap + k0);
            float4 bv = *(const float4*)(Bp + k0);
            __syncthreads();
            As[akv*4+0][ar]=av.x; As[akv*4+1][ar]=av.y;
            As[akv*4+2][ar]=av.z; As[akv*4+3][ar]=av.w;
            Bs[akv*4+0][ar]=bv.x; Bs[akv*4+1][ar]=bv.y;
            Bs[akv*4+2][ar]=bv.z; Bs[akv*4+3][ar]=bv.w;
            __syncthreads();
            #pragma unroll
            for (int k = 0; k < 16; k++) {
                float4 a = *(const float4*)&As[k][tm * 4];
                float4 b = *(const float4*)&Bs[k][tn * 4];
                acc[0][0]+=a.x*b.x; acc[0][1]+=a.x*b.y; acc[0][2]+=a.x*b.z; acc[0][3]+=a.x*b.w;
                acc[1][0]+=a.y*b.x; acc[1][1]+=a.y*b.y; acc[1][2]+=a.y*b.z; acc[1][3]+=a.y*b.w;
                acc[2][0]+=a.z*b.x; acc[2][1]+=a.z*b.y; acc[2][2]+=a.z*b.z; acc[2][3]+=a.z*b.w;
                acc[3][0]+=a.w*b.x; acc[3][1]+=a.w*b.y; acc[3][2]+=a.w*b.z; acc[3][3]+=a.w*b.w;
            }
        }
        float* P = g_part[kh];
        const int row = row0 + tm * 4;
        const int col = bn * 64 + tn * 4;
        #pragma unroll
        for (int i = 0; i < 4; i++)
            *(float4*)&P[(size_t)(row + i) * H_ + col] =
                make_float4(acc[i][0], acc[i][1], acc[i][2], acc[i][3]);
        return;
    }

    // ---------------- Means role (DRAM-bound)
    if (role == 1) {
        const int b = meansRow + idx;
        const int h4 = tid & 127;
        const bool isimg = (tid < 128);
        const float* src = isimg ? img : txt;
        const float4* base = (const float4*)(src + (size_t)b * MND * H_) + h4;

        float4 acc = make_float4(0.f, 0.f, 0.f, 0.f);
        #pragma unroll 16
        for (int m = 0; m < MND; m++) {
            float4 v = base[(size_t)m * (H_ / 4)];
            acc.x += v.x; acc.y += v.y; acc.z += v.z; acc.w += v.w;
        }
        const float inv = 1.0f / (float)MND;
        acc.x *= inv; acc.y *= inv; acc.z *= inv; acc.w *= inv;

        float4* xrow = (float4*)(g_X + (size_t)b * KF);
        xrow[(isimg ? 0 : 128) + h4] = acc;

        const float4* cs = (const float4*)((isimg ? it : ii) + (size_t)b * D_);
        xrow[(isimg ? 256 : 384) + h4] = cs[h4];
        return;
    }

    // ---------------- Epilogue role: out = relu(sum of 4 partials + bc)
    if (role == 2) {
        const int b = epiRow + idx * 2 + (tid >> 7);
        const int c4 = tid & 127;
        const size_t o = (size_t)b * H_ + c4 * 4;
        float4 s0 = *(const float4*)&g_part[0][o];
        float4 s1 = *(const float4*)&g_part[1][o];
        float4 s2 = *(const float4*)&g_part[2][o];
        float4 s3 = *(const float4*)&g_part[3][o];
        float4 bias = *(const float4*)&g_bc[c4 * 4];
        float4 v;
        v.x = fmaxf(s0.x + s1.x + s2.x + s3.x + bias.x, 0.f);
        v.y = fmaxf(s0.y + s1.y + s2.y + s3.y + bias.y, 0.f);
        v.z = fmaxf(s0.z + s1.z + s2.z + s3.z + bias.z, 0.f);
        v.w = fmaxf(s0.w + s1.w + s2.w + s3.w + bias.w, 0.f);
        *(float4*)&out[o] = v;
        return;
    }

    // ---------------- wc role (128 blocks): Wbig[:,1024:2048) = (Wr_img+Wr_txt) @ W_user
    if (role == 3) {
        const int bn = idx & 15;          // 1024/64
        const int bm = idx >> 4;          // 512/64
        const int tn = tid & 15, tm = tid >> 4;
        const int ar = tid >> 2, akv = tid & 3;
        const int brow = tid >> 4, bc4 = tid & 15;

        const size_t aoff = (size_t)(bm * 64 + ar) * 512 + akv * 4;
        const float* Bp = Wuser + (size_t)brow * 1024 + bn * 64 + bc4 * 4;

        float acc[4][4] = {};
        for (int k0 = 0; k0 < 512; k0 += 16) {
            float4 a1 = *(const float4*)(Wr_img + aoff + k0);
            float4 a2 = *(const float4*)(Wr_txt + aoff + k0);
            float4 av = make_float4(a1.x + a2.x, a1.y + a2.y, a1.z + a2.z, a1.w + a2.w);
            float4 bv = *(const float4*)(Bp + (size_t)k0 * 1024);
            __syncthreads();
            As[akv*4+0][ar]=av.x; As[akv*4+1][ar]=av.y;
            As[akv*4+2][ar]=av.z; As[akv*4+3][ar]=av.w;
            *(float4*)&Bs[brow][bc4 * 4] = bv;
            __syncthreads();
            #pragma unroll
            for (int k = 0; k < 16; k++) {
                float4 a = *(const float4*)&As[k][tm * 4];
                float4 b = *(const float4*)&Bs[k][tn * 4];
                acc[0][0]+=a.x*b.x; acc[0][1]+=a.x*b.y; acc[0][2]+=a.x*b.z; acc[0][3]+=a.x*b.w;
                acc[1][0]+=a.y*b.x; acc[1][1]+=a.y*b.y; acc[1][2]+=a.y*b.z; acc[1][3]+=a.y*b.w;
                acc[2][0]+=a.z*b.x; acc[2][1]+=a.z*b.y; acc[2][2]+=a.z*b.z; acc[2][3]+=a.z*b.w;
                acc[3][0]+=a.w*b.x; acc[3][1]+=a.w*b.y; acc[3][2]+=a.w*b.z; acc[3][3]+=a.w*b.w;
            }
        }
        const int row = bm * 64 + tm * 4;
        const int col = bn * 64 + tn * 4;
        #pragma unroll
        for (int i = 0; i < 4; i++)
            *(float4*)&g_Wbig[(size_t)(row + i) * KF + 1024 + col] =
                make_float4(acc[i][0], acc[i][1], acc[i][2], acc[i][3]);
        return;
    }

    // ---------------- prep role (256 blocks): Wbig[:,0:1024) = [Wl_img | Wl_txt]
    if (role == 4) {
        #pragma unroll
        for (int j = 0; j < 2; j++) {
            int q = idx * 256 + tid + j * 65536;   // float4 index over 512x1024
            int h = q >> 8, c4 = q & 255;
            int c = c4 * 4;
            float4 v = (c < 512)
                ? *(const float4*)(Wl_img + (size_t)h * 512 + c)
                : *(const float4*)(Wl_txt + (size_t)h * 512 + (c - 512));
            *(float4*)&g_Wbig[(size_t)h * KF + c] = v;
        }
        return;
    }

    // ---------------- bc role (512 blocks)
    {
        const int h = idx;
        float s = 0.0f;
        #pragma unroll
        for (int j = 0; j < 2; j++) {
            int k = tid + j * 256;
            s += (Wr_img[(size_t)h * 512 + k] + Wr_txt[(size_t)h * 512 + k]) * b_user[k];
        }
        #pragma unroll
        for (int o = 16; o; o >>= 1) s += __shfl_down_sync(0xffffffffu, s, o);
        if ((tid & 31) == 0) red8[tid >> 5] = s;
        __syncthreads();
        if (tid == 0) {
            float t = 0.f;
            #pragma unroll
            for (int i = 0; i < 8; i++) t += red8[i];
            g_bc[h] = t + bl_img[h] + bl_txt[h];
        }
        return;
    }
}

// ---------------------------------------------------------------------------
extern "C" void kernel_launch(void* const* d_in, const int* in_sizes, int n_in,
                              void* d_out, int out_size) {
    const float* it      = (const float*)d_in[0];
    const float* ii      = (const float*)d_in[1];
    const float* txt     = (const float*)d_in[2];
    const float* img     = (const float*)d_in[3];
    const float* W_user  = (const float*)d_in[4];
    const float* b_user  = (const float*)d_in[5];
    const float* Wl_img  = (const float*)d_in[6];
    const float* bl_img  = (const float*)d_in[7];
    const float* Wr_img  = (const float*)d_in[8];
    const float* Wl_txt  = (const float*)d_in[9];
    const float* bl_txt  = (const float*)d_in[10];
    const float* Wr_txt  = (const float*)d_in[11];
    float* out = (float*)d_out;

    #define MEGA(grid, pat, gr, mr, er)                                         \
        mega_kernel<<<(grid), 256>>>(img, txt, it, ii, Wl_img, Wl_txt,          \
            Wr_img, Wr_txt, W_user, b_user, bl_img, bl_txt, out,                \
            (pat), (gr), (mr), (er))

    // S0: means(c0) + setup (wc 128 first, then means/prep/bc)
    MEGA(1408, 0, 0, 0,    0);
    // S1: gemm(c0) + means(c1), interleaved period-3
    MEGA(768,  1, 0, 512,  0);
    // S2: gemm(c1) + means(c2) + epi(c0), interleaved period-4
    MEGA(1024, 2, 512, 1024, 0);
    // S3: gemm(c2) + means(c3) + epi(c1)
    MEGA(1024, 2, 1024, 1536, 512);
    // S4: gemm(c3) + epi(c2)
    MEGA(512,  3, 1536, 0, 1024);
    // S5: epi(c3)
    MEGA(256,  4, 0, 0, 1536);

    #undef MEGA
}

// round 12
// speedup vs baseline: 1.3321x; 1.3321x over previous
#include <cuda_runtime.h>
#include <cstdint>

// Problem constants
#define B_   2048
#define MND  128
#define D_   512
#define H_   512
#define KF   2048    // GEMM K = 4*512

// Scratch (device globals; no allocations allowed)
__device__ float g_X[(size_t)B_ * KF];     // [2048,2048] = [img_mean|txt_mean|it|ii]
__device__ float g_Wbig[(size_t)H_ * KF];  // [512,2048]  = [W_l_img|W_l_txt|Wc]
__device__ float g_bc[H_];                 // combined bias

// ---------------------------------------------------------------------------
// setup: one launch, 896 blocks.
//   [0,128)   wc   : Wbig[:,1024:2048) = (Wr_img+Wr_txt) @ W_user
//   [128,384) prep : Wbig[:,0:1024)    = [Wl_img | Wl_txt]
//   [384,896) bc   : bc[h]
// ---------------------------------------------------------------------------
__global__ __launch_bounds__(256) void setup_kernel(
    const float* __restrict__ Wl_img, const float* __restrict__ Wl_txt,
    const float* __restrict__ Wr_img, const float* __restrict__ Wr_txt,
    const float* __restrict__ Wuser,  const float* __restrict__ b_user,
    const float* __restrict__ bl_img, const float* __restrict__ bl_txt)
{
    __shared__ float As[16][68];
    __shared__ float Bs[16][68];
    __shared__ float red8[8];
    const int tid = threadIdx.x;
    int bid = blockIdx.x;

    if (bid < 128) {   // ---- wc role
        const int bn = bid & 15;          // 1024/64
        const int bm = bid >> 4;          // 512/64
        const int tn = tid & 15, tm = tid >> 4;
        const int ar = tid >> 2, akv = tid & 3;
        const int brow = tid >> 4, bc4 = tid & 15;

        const size_t aoff = (size_t)(bm * 64 + ar) * 512 + akv * 4;
        const float* Bp = Wuser + (size_t)brow * 1024 + bn * 64 + bc4 * 4;

        float acc[4][4] = {};
        for (int k0 = 0; k0 < 512; k0 += 16) {
            float4 a1 = *(const float4*)(Wr_img + aoff + k0);
            float4 a2 = *(const float4*)(Wr_txt + aoff + k0);
            float4 av = make_float4(a1.x + a2.x, a1.y + a2.y, a1.z + a2.z, a1.w + a2.w);
            float4 bv = *(const float4*)(Bp + (size_t)k0 * 1024);
            __syncthreads();
            As[akv*4+0][ar]=av.x; As[akv*4+1][ar]=av.y;
            As[akv*4+2][ar]=av.z; As[akv*4+3][ar]=av.w;
            *(float4*)&Bs[brow][bc4 * 4] = bv;
            __syncthreads();
            #pragma unroll
            for (int k = 0; k < 16; k++) {
                float4 a = *(const float4*)&As[k][tm * 4];
                float4 b = *(const float4*)&Bs[k][tn * 4];
                acc[0][0]+=a.x*b.x; acc[0][1]+=a.x*b.y; acc[0][2]+=a.x*b.z; acc[0][3]+=a.x*b.w;
                acc[1][0]+=a.y*b.x; acc[1][1]+=a.y*b.y; acc[1][2]+=a.y*b.z; acc[1][3]+=a.y*b.w;
                acc[2][0]+=a.z*b.x; acc[2][1]+=a.z*b.y; acc[2][2]+=a.z*b.z; acc[2][3]+=a.z*b.w;
                acc[3][0]+=a.w*b.x; acc[3][1]+=a.w*b.y; acc[3][2]+=a.w*b.z; acc[3][3]+=a.w*b.w;
            }
        }
        const int row = bm * 64 + tm * 4;
        const int col = bn * 64 + tn * 4;
        #pragma unroll
        for (int i = 0; i < 4; i++)
            *(float4*)&g_Wbig[(size_t)(row + i) * KF + 1024 + col] =
                make_float4(acc[i][0], acc[i][1], acc[i][2], acc[i][3]);
        return;
    }
    bid -= 128;

    if (bid < 256) {   // ---- prep role
        #pragma unroll
        for (int j = 0; j < 2; j++) {
            int q = bid * 256 + tid + j * 65536;   // float4 index over 512x1024
            int h = q >> 8, c4 = q & 255;
            int c = c4 * 4;
            float4 v = (c < 512)
                ? *(const float4*)(Wl_img + (size_t)h * 512 + c)
                : *(const float4*)(Wl_txt + (size_t)h * 512 + (c - 512));
            *(float4*)&g_Wbig[(size_t)h * KF + c] = v;
        }
        return;
    }
    bid -= 256;

    {   // ---- bc role (512 blocks)
        const int h = bid;
        float s = 0.0f;
        #pragma unroll
        for (int j = 0; j < 2; j++) {
            int k = tid + j * 256;
            s += (Wr_img[(size_t)h * 512 + k] + Wr_txt[(size_t)h * 512 + k]) * b_user[k];
        }
        #pragma unroll
        for (int o = 16; o; o >>= 1) s += __shfl_down_sync(0xffffffffu, s, o);
        if ((tid & 31) == 0) red8[tid >> 5] = s;
        __syncthreads();
        if (tid == 0) {
            float t = 0.f;
            #pragma unroll
            for (int i = 0; i < 8; i++) t += red8[i];
            g_bc[h] = t + bl_img[h] + bl_txt[h];
        }
    }
}

// ---------------------------------------------------------------------------
// means: X[b] = [mean img | mean txt | it | ii]   (proven: 86% DRAM)
// ---------------------------------------------------------------------------
__global__ void means_kernel(const float* __restrict__ img,
                             const float* __restrict__ txt,
                             const float* __restrict__ it,
                             const float* __restrict__ ii) {
    int b = blockIdx.x;
    int t = threadIdx.x;
    int h4 = t & 127;
    const bool isimg = (t < 128);
    const float* src = isimg ? img : txt;
    const float4* base = (const float4*)(src + (size_t)b * MND * H_) + h4;

    float4 acc = make_float4(0.f, 0.f, 0.f, 0.f);
    #pragma unroll 16
    for (int m = 0; m < MND; m++) {
        float4 v = base[(size_t)m * (H_ / 4)];
        acc.x += v.x; acc.y += v.y; acc.z += v.z; acc.w += v.w;
    }
    const float inv = 1.0f / (float)MND;
    acc.x *= inv; acc.y *= inv; acc.z *= inv; acc.w *= inv;

    float4* xrow = (float4*)(g_X + (size_t)b * KF);
    xrow[(isimg ? 0 : 128) + h4] = acc;

    const float4* cs = (const float4*)((isimg ? it : ii) + (size_t)b * D_);
    xrow[(isimg ? 256 : 384) + h4] = cs[h4];
}

// ---------------------------------------------------------------------------
// Hybrid GEMM: tile 128(M) x 64(N), K=2048, 256 threads, 128 CTAs (one wave).
//   warps 4-7: tile rows [0,64)   via tf32 mma.sync (tensor pipe)
//   warps 0-3: tile rows [64,128) via FFMA-SIMT      (fma pipe)
// One mma warp + one SIMT warp per SMSP -> both pipes busy concurrently.
// Shared smem k-loop; fused bias + ReLU epilogue. No partials.
// ---------------------------------------------------------------------------
__device__ __forceinline__ uint32_t tf32c(float x) {
    uint32_t u;
    asm("cvt.rna.tf32.f32 %0, %1;" : "=r"(u) : "f"(x));
    return u;
}

__global__ __launch_bounds__(256) void gemm_hybrid(float* __restrict__ C) {
    __shared__ float As[16][132];   // [k][m], 128 rows + pad
    __shared__ float Bs[16][68];    // [k][n], 64 cols + pad

    const int tid  = threadIdx.x;
    const int wid  = tid >> 5;
    const int lane = tid & 31;
    const int bn0  = blockIdx.x * 64;
    const int bm0  = blockIdx.y * 128;

    // loader mapping (all 256 threads)
    const int ar  = tid >> 2;       // 0..63
    const int akv = tid & 3;        // k-offset group
    const float* ApA = g_X    + (size_t)(bm0 + ar) * KF + akv * 4;        // rows 0..63
    const float* ApB = g_X    + (size_t)(bm0 + 64 + ar) * KF + akv * 4;   // rows 64..127
    const float* Bp  = g_Wbig + (size_t)(bn0 + ar) * KF + akv * 4;

    const bool simt = (wid < 4);
    // SIMT mapping: 128 threads (warps 0-3): 8 rows x 4 cols per thread
    const int tn = tid & 15;          // 0..15
    const int tm = (tid >> 4) & 7;    // 0..7
    // mma mapping: warp wq handles tile rows wq*16..+16
    const int wq = wid - 4;
    const int g  = lane >> 2;
    const int tg = lane & 3;

    float acc[8][4];
    #pragma unroll
    for (int i = 0; i < 8; i++)
        #pragma unroll
        for (int j = 0; j < 4; j++) acc[i][j] = 0.f;

    for (int k0 = 0; k0 < KF; k0 += 16) {
        float4 av0 = *(const float4*)(ApA + k0);
        float4 av1 = *(const float4*)(ApB + k0);
        float4 bv  = *(const float4*)(Bp  + k0);
        __syncthreads();
        As[akv*4+0][ar]      = av0.x; As[akv*4+1][ar]      = av0.y;
        As[akv*4+2][ar]      = av0.z; As[akv*4+3][ar]      = av0.w;
        As[akv*4+0][ar + 64] = av1.x; As[akv*4+1][ar + 64] = av1.y;
        As[akv*4+2][ar + 64] = av1.z; As[akv*4+3][ar + 64] = av1.w;
        Bs[akv*4+0][ar] = bv.x; Bs[akv*4+1][ar] = bv.y;
        Bs[akv*4+2][ar] = bv.z; Bs[akv*4+3][ar] = bv.w;
        __syncthreads();

        if (simt) {
            // rows 64..127 : exact fp32 FFMA
            #pragma unroll
            for (int k = 0; k < 16; k++) {
                float4 b  = *(const float4*)&Bs[k][tn * 4];
                float4 a0 = *(const float4*)&As[k][64 + tm * 8];
                float4 a1 = *(const float4*)&As[k][64 + tm * 8 + 4];
                acc[0][0]+=a0.x*b.x; acc[0][1]+=a0.x*b.y; acc[0][2]+=a0.x*b.z; acc[0][3]+=a0.x*b.w;
                acc[1][0]+=a0.y*b.x; acc[1][1]+=a0.y*b.y; acc[1][2]+=a0.y*b.z; acc[1][3]+=a0.y*b.w;
                acc[2][0]+=a0.z*b.x; acc[2][1]+=a0.z*b.y; acc[2][2]+=a0.z*b.z; acc[2][3]+=a0.z*b.w;
                acc[3][0]+=a0.w*b.x; acc[3][1]+=a0.w*b.y; acc[3][2]+=a0.w*b.z; acc[3][3]+=a0.w*b.w;
                acc[4][0]+=a1.x*b.x; acc[4][1]+=a1.x*b.y; acc[4][2]+=a1.x*b.z; acc[4][3]+=a1.x*b.w;
                acc[5][0]+=a1.y*b.x; acc[5][1]+=a1.y*b.y; acc[5][2]+=a1.y*b.z; acc[5][3]+=a1.y*b.w;
                acc[6][0]+=a1.z*b.x; acc[6][1]+=a1.z*b.y; acc[6][2]+=a1.z*b.z; acc[6][3]+=a1.z*b.w;
                acc[7][0]+=a1.w*b.x; acc[7][1]+=a1.w*b.y; acc[7][2]+=a1.w*b.z; acc[7][3]+=a1.w*b.w;
            }
        } else {
            // rows 0..63 : tf32 mma (tensor pipe); cvt.rna after LDS
            const int m0 = wq * 16;
            #pragma unroll
            for (int kc = 0; kc < 16; kc += 8) {
                uint32_t a[4];
                a[0] = tf32c(As[kc + tg][m0 + g]);
                a[1] = tf32c(As[kc + tg][m0 + g + 8]);
                a[2] = tf32c(As[kc + tg + 4][m0 + g]);
                a[3] = tf32c(As[kc + tg + 4][m0 + g + 8]);
                #pragma unroll
                for (int n = 0; n < 8; n++) {
                    uint32_t b0 = tf32c(Bs[kc + tg][n * 8 + g]);
                    uint32_t b1 = tf32c(Bs[kc + tg + 4][n * 8 + g]);
                    asm volatile(
                        "mma.sync.aligned.m16n8k8.row.col.f32.tf32.tf32.f32 "
                        "{%0,%1,%2,%3}, {%4,%5,%6,%7}, {%8,%9}, {%0,%1,%2,%3};\n"
                        : "+f"(acc[n][0]), "+f"(acc[n][1]),
                          "+f"(acc[n][2]), "+f"(acc[n][3])
                        : "r"(a[0]), "r"(a[1]), "r"(a[2]), "r"(a[3]),
                          "r"(b0), "r"(b1));
                }
            }
        }
    }

    // epilogue: bias + ReLU
    if (simt) {
        const int row0 = bm0 + 64 + tm * 8;
        const int col  = bn0 + tn * 4;
        float4 bias = *(const float4*)&g_bc[col];
        #pragma unroll
        for (int i = 0; i < 8; i++) {
            float4 v;
            v.x = fmaxf(acc[i][0] + bias.x, 0.f);
            v.y = fmaxf(acc[i][1] + bias.y, 0.f);
            v.z = fmaxf(acc[i][2] + bias.z, 0.f);
            v.w = fmaxf(acc[i][3] + bias.w, 0.f);
            *(float4*)&C[(size_t)(row0 + i) * H_ + col] = v;
        }
    } else {
        const int row0 = bm0 + wq * 16 + g;
        #pragma unroll
        for (int n = 0; n < 8; n++) {
            const int col = bn0 + n * 8 + tg * 2;
            const float b0v = g_bc[col], b1v = g_bc[col + 1];
            float2 v0, v1;
            v0.x = fmaxf(acc[n][0] + b0v, 0.f);
            v0.y = fmaxf(acc[n][1] + b1v, 0.f);
            v1.x = fmaxf(acc[n][2] + b0v, 0.f);
            v1.y = fmaxf(acc[n][3] + b1v, 0.f);
            *(float2*)&C[(size_t)row0 * H_ + col]       = v0;
            *(float2*)&C[(size_t)(row0 + 8) * H_ + col] = v1;
        }
    }
}

// ---------------------------------------------------------------------------
extern "C" void kernel_launch(void* const* d_in, const int* in_sizes, int n_in,
                              void* d_out, int out_size) {
    const float* it      = (const float*)d_in[0];
    const float* ii      = (const float*)d_in[1];
    const float* txt     = (const float*)d_in[2];
    const float* img     = (const float*)d_in[3];
    const float* W_user  = (const float*)d_in[4];
    const float* b_user  = (const float*)d_in[5];
    const float* Wl_img  = (const float*)d_in[6];
    const float* bl_img  = (const float*)d_in[7];
    const float* Wr_img  = (const float*)d_in[8];
    const float* Wl_txt  = (const float*)d_in[9];
    const float* bl_txt  = (const float*)d_in[10];
    const float* Wr_txt  = (const float*)d_in[11];
    float* out = (float*)d_out;

    // 1) weight setup (one launch)
    setup_kernel<<<896, 256>>>(Wl_img, Wl_txt, Wr_img, Wr_txt,
                               W_user, b_user, bl_img, bl_txt);

    // 2) means (HBM-bound, proven at 86% of peak)
    means_kernel<<<B_, 256>>>(img, txt, it, ii);

    // 3) hybrid FFMA+tensor GEMM: out = relu(X @ Wbig^T + bc)
    {
        dim3 grid(H_ / 64, B_ / 128);   // (8, 16) = 128 CTAs, one wave
        gemm_hybrid<<<grid, 256>>>(out);
    }
}

// round 13
// speedup vs baseline: 1.5205x; 1.1414x over previous
#include <cuda_runtime.h>
#include <cstdint>

// Problem constants
#define B_   2048
#define MND  128
#define D_   512
#define H_   512
#define KF   2048    // GEMM K = 4*512

// Scratch (device globals; no allocations allowed)
__device__ float g_X[(size_t)B_ * KF];     // [2048,2048] = [img_mean|txt_mean|it|ii]
__device__ float g_Wbig[(size_t)H_ * KF];  // [512,2048]  = [W_l_img|W_l_txt|Wc]
__device__ float g_bc[H_];                 // combined bias

// ===========================================================================
// Launch 1: fused means + weight-setup. 2944 blocks, 256 threads.
//   [0,128)      wc   : Wbig[:,1024:2048) = (Wr_img+Wr_txt) @ W_user  (prefetched)
//   [128,640)    bc   : combined bias
//   [640,896)    prep : Wbig[:,0:1024) = [Wl_img | Wl_txt]
//   [896,2944)   means: X[b] = [img_mean | txt_mean | it | ii]
// Setup blocks are latency/compute-bound and hide under the DRAM-bound means.
// ===========================================================================
__global__ __launch_bounds__(256) void fused_means_setup(
    const float* __restrict__ img,    const float* __restrict__ txt,
    const float* __restrict__ it,     const float* __restrict__ ii,
    const float* __restrict__ Wl_img, const float* __restrict__ Wl_txt,
    const float* __restrict__ Wr_img, const float* __restrict__ Wr_txt,
    const float* __restrict__ Wuser,  const float* __restrict__ b_user,
    const float* __restrict__ bl_img, const float* __restrict__ bl_txt)
{
    __shared__ float As[16][68];
    __shared__ float Bs[16][68];
    __shared__ float red8[8];
    const int tid = threadIdx.x;
    int bid = blockIdx.x;

    if (bid < 128) {   // ---- wc role (register-prefetch double buffered)
        const int bn = bid & 15;          // 1024/64
        const int bm = bid >> 4;          // 512/64
        const int tn = tid & 15, tm = tid >> 4;
        const int ar = tid >> 2, akv = tid & 3;
        const int brow = tid >> 4, bc4 = tid & 15;

        const size_t aoff = (size_t)(bm * 64 + ar) * 512 + akv * 4;
        const float* Bp = Wuser + (size_t)brow * 1024 + bn * 64 + bc4 * 4;

        float acc[4][4] = {};
        float4 a1 = *(const float4*)(Wr_img + aoff);
        float4 a2 = *(const float4*)(Wr_txt + aoff);
        float4 bv = *(const float4*)(Bp);
        for (int k0 = 0; k0 < 512; k0 += 16) {
            float4 av = make_float4(a1.x + a2.x, a1.y + a2.y, a1.z + a2.z, a1.w + a2.w);
            float4 bcur = bv;
            __syncthreads();
            As[akv*4+0][ar]=av.x; As[akv*4+1][ar]=av.y;
            As[akv*4+2][ar]=av.z; As[akv*4+3][ar]=av.w;
            *(float4*)&Bs[brow][bc4 * 4] = bcur;
            __syncthreads();
            if (k0 + 16 < 512) {   // prefetch next tile while computing
                a1 = *(const float4*)(Wr_img + aoff + k0 + 16);
                a2 = *(const float4*)(Wr_txt + aoff + k0 + 16);
                bv = *(const float4*)(Bp + (size_t)(k0 + 16) * 1024);
            }
            #pragma unroll
            for (int k = 0; k < 16; k++) {
                float4 a = *(const float4*)&As[k][tm * 4];
                float4 b = *(const float4*)&Bs[k][tn * 4];
                acc[0][0]+=a.x*b.x; acc[0][1]+=a.x*b.y; acc[0][2]+=a.x*b.z; acc[0][3]+=a.x*b.w;
                acc[1][0]+=a.y*b.x; acc[1][1]+=a.y*b.y; acc[1][2]+=a.y*b.z; acc[1][3]+=a.y*b.w;
                acc[2][0]+=a.z*b.x; acc[2][1]+=a.z*b.y; acc[2][2]+=a.z*b.z; acc[2][3]+=a.z*b.w;
                acc[3][0]+=a.w*b.x; acc[3][1]+=a.w*b.y; acc[3][2]+=a.w*b.z; acc[3][3]+=a.w*b.w;
            }
        }
        const int row = bm * 64 + tm * 4;
        const int col = bn * 64 + tn * 4;
        #pragma unroll
        for (int i = 0; i < 4; i++)
            *(float4*)&g_Wbig[(size_t)(row + i) * KF + 1024 + col] =
                make_float4(acc[i][0], acc[i][1], acc[i][2], acc[i][3]);
        return;
    }
    bid -= 128;

    if (bid < 512) {   // ---- bc role
        const int h = bid;
        float s = 0.0f;
        #pragma unroll
        for (int j = 0; j < 2; j++) {
            int k = tid + j * 256;
            s += (Wr_img[(size_t)h * 512 + k] + Wr_txt[(size_t)h * 512 + k]) * b_user[k];
        }
        #pragma unroll
        for (int o = 16; o; o >>= 1) s += __shfl_down_sync(0xffffffffu, s, o);
        if ((tid & 31) == 0) red8[tid >> 5] = s;
        __syncthreads();
        if (tid == 0) {
            float t = 0.f;
            #pragma unroll
            for (int i = 0; i < 8; i++) t += red8[i];
            g_bc[h] = t + bl_img[h] + bl_txt[h];
        }
        return;
    }
    bid -= 512;

    if (bid < 256) {   // ---- prep role
        #pragma unroll
        for (int j = 0; j < 2; j++) {
            int q = bid * 256 + tid + j * 65536;   // float4 index over 512x1024
            int h = q >> 8, c4 = q & 255;
            int c = c4 * 4;
            float4 v = (c < 512)
                ? *(const float4*)(Wl_img + (size_t)h * 512 + c)
                : *(const float4*)(Wl_txt + (size_t)h * 512 + (c - 512));
            *(float4*)&g_Wbig[(size_t)h * KF + c] = v;
        }
        return;
    }
    bid -= 256;

    {   // ---- means role (2048 blocks; proven 86% DRAM structure)
        const int b = bid;
        const int h4 = tid & 127;
        const bool isimg = (tid < 128);
        const float* src = isimg ? img : txt;
        const float4* base = (const float4*)(src + (size_t)b * MND * H_) + h4;

        float4 acc = make_float4(0.f, 0.f, 0.f, 0.f);
        #pragma unroll 16
        for (int m = 0; m < MND; m++) {
            float4 v = base[(size_t)m * (H_ / 4)];
            acc.x += v.x; acc.y += v.y; acc.z += v.z; acc.w += v.w;
        }
        const float inv = 1.0f / (float)MND;
        acc.x *= inv; acc.y *= inv; acc.z *= inv; acc.w *= inv;

        float4* xrow = (float4*)(g_X + (size_t)b * KF);
        xrow[(isimg ? 0 : 128) + h4] = acc;

        const float4* cs = (const float4*)((isimg ? it : ii) + (size_t)b * D_);
        xrow[(isimg ? 256 : 384) + h4] = cs[h4];
    }
}

// ===========================================================================
// Launch 2: out = relu( X @ Wbig^T + bc ), exact fp32 FFMA (measured roofline
// ~130us). 64x64 tiles, 256 threads, 4x4/thread, register-prefetch k-loop.
// ===========================================================================
__global__ __launch_bounds__(256) void gemm_out(float* __restrict__ C) {
    __shared__ float As[16][68];
    __shared__ float Bs[16][68];
    const int bn = blockIdx.x;
    const int bm = blockIdx.y;
    const int tid = threadIdx.x;
    const int tn = tid & 15, tm = tid >> 4;
    const int ar = tid >> 2, akv = tid & 3;

    const float* Ap = g_X    + (size_t)(bm * 64 + ar) * KF + akv * 4;
    const float* Bp = g_Wbig + (size_t)(bn * 64 + ar) * KF + akv * 4;

    float acc[4][4] = {};
    float4 av = *(const float4*)(Ap);
    float4 bv = *(const float4*)(Bp);
    for (int k0 = 0; k0 < KF; k0 += 16) {
        float4 acur = av, bcur = bv;
        __syncthreads();
        As[akv*4+0][ar]=acur.x; As[akv*4+1][ar]=acur.y;
        As[akv*4+2][ar]=acur.z; As[akv*4+3][ar]=acur.w;
        Bs[akv*4+0][ar]=bcur.x; Bs[akv*4+1][ar]=bcur.y;
        Bs[akv*4+2][ar]=bcur.z; Bs[akv*4+3][ar]=bcur.w;
        __syncthreads();
        if (k0 + 16 < KF) {    // prefetch next tile; latency hidden by compute
            av = *(const float4*)(Ap + k0 + 16);
            bv = *(const float4*)(Bp + k0 + 16);
        }
        #pragma unroll
        for (int k = 0; k < 16; k++) {
            float4 a = *(const float4*)&As[k][tm * 4];
            float4 b = *(const float4*)&Bs[k][tn * 4];
            acc[0][0]+=a.x*b.x; acc[0][1]+=a.x*b.y; acc[0][2]+=a.x*b.z; acc[0][3]+=a.x*b.w;
            acc[1][0]+=a.y*b.x; acc[1][1]+=a.y*b.y; acc[1][2]+=a.y*b.z; acc[1][3]+=a.y*b.w;
            acc[2][0]+=a.z*b.x; acc[2][1]+=a.z*b.y; acc[2][2]+=a.z*b.z; acc[2][3]+=a.z*b.w;
            acc[3][0]+=a.w*b.x; acc[3][1]+=a.w*b.y; acc[3][2]+=a.w*b.z; acc[3][3]+=a.w*b.w;
        }
    }

    const int row = bm * 64 + tm * 4;
    const int col = bn * 64 + tn * 4;
    float4 bias = *(const float4*)&g_bc[col];
    #pragma unroll
    for (int i = 0; i < 4; i++) {
        float4 v;
        v.x = fmaxf(acc[i][0] + bias.x, 0.f);
        v.y = fmaxf(acc[i][1] + bias.y, 0.f);
        v.z = fmaxf(acc[i][2] + bias.z, 0.f);
        v.w = fmaxf(acc[i][3] + bias.w, 0.f);
        *(float4*)&C[(size_t)(row + i) * H_ + col] = v;
    }
}

// ---------------------------------------------------------------------------
extern "C" void kernel_launch(void* const* d_in, const int* in_sizes, int n_in,
                              void* d_out, int out_size) {
    const float* it      = (const float*)d_in[0];
    const float* ii      = (const float*)d_in[1];
    const float* txt     = (const float*)d_in[2];
    const float* img     = (const float*)d_in[3];
    const float* W_user  = (const float*)d_in[4];
    const float* b_user  = (const float*)d_in[5];
    const float* Wl_img  = (const float*)d_in[6];
    const float* bl_img  = (const float*)d_in[7];
    const float* Wr_img  = (const float*)d_in[8];
    const float* Wl_txt  = (const float*)d_in[9];
    const float* bl_txt  = (const float*)d_in[10];
    const float* Wr_txt  = (const float*)d_in[11];
    float* out = (float*)d_out;

    // Launch 1: means + all weight setup fused (setup hides under DRAM phase)
    fused_means_setup<<<2944, 256>>>(img, txt, it, ii, Wl_img, Wl_txt,
                                     Wr_img, Wr_txt, W_user, b_user,
                                     bl_img, bl_txt);

    // Launch 2: FFMA GEMM at the measured fp32 roofline
    {
        dim3 grid(H_ / 64, B_ / 64);   // (8, 32) = 256 CTAs
        gemm_out<<<grid, 256>>>(out);
    }
}

// round 16
// speedup vs baseline: 1.5715x; 1.0336x over previous
#include <cuda_runtime.h>
#include <cstdint>

// Problem constants
#define B_   2048
#define MND  128
#define D_   512
#define H_   512
#define KF   2048    // GEMM K = 4*512
#define KSEG 512     // split-K segment
#define NKH  4

// Scratch (device globals; no allocations allowed)
__device__ float g_X[(size_t)B_ * KF];           // [2048,2048]
__device__ float g_Wbig[(size_t)H_ * KF];        // [512,2048]
__device__ float g_bc[H_];                       // combined bias
__device__ float g_part[NKH][(size_t)B_ * H_];   // split-K partials

// ===========================================================================
// Launch 1: fused means + weight-setup (proven: setup hides under DRAM phase)
//   [0,128) wc | [128,640) bc | [640,896) prep | [896,2944) means
// ===========================================================================
__global__ __launch_bounds__(256) void fused_means_setup(
    const float* __restrict__ img,    const float* __restrict__ txt,
    const float* __restrict__ it,     const float* __restrict__ ii,
    const float* __restrict__ Wl_img, const float* __restrict__ Wl_txt,
    const float* __restrict__ Wr_img, const float* __restrict__ Wr_txt,
    const float* __restrict__ Wuser,  const float* __restrict__ b_user,
    const float* __restrict__ bl_img, const float* __restrict__ bl_txt)
{
    __shared__ float As[16][68];
    __shared__ float Bs[16][68];
    __shared__ float red8[8];
    const int tid = threadIdx.x;
    int bid = blockIdx.x;

    if (bid < 128) {   // ---- wc: Wbig[:,1024:2048) = (Wr_img+Wr_txt) @ W_user
        const int bn = bid & 15;
        const int bm = bid >> 4;
        const int tn = tid & 15, tm = tid >> 4;
        const int ar = tid >> 2, akv = tid & 3;
        const int brow = tid >> 4, bc4 = tid & 15;

        const size_t aoff = (size_t)(bm * 64 + ar) * 512 + akv * 4;
        const float* Bp = Wuser + (size_t)brow * 1024 + bn * 64 + bc4 * 4;

        float acc[4][4] = {};
        float4 a1 = *(const float4*)(Wr_img + aoff);
        float4 a2 = *(const float4*)(Wr_txt + aoff);
        float4 bv = *(const float4*)(Bp);
        for (int k0 = 0; k0 < 512; k0 += 16) {
            float4 av = make_float4(a1.x + a2.x, a1.y + a2.y, a1.z + a2.z, a1.w + a2.w);
            float4 bcur = bv;
            __syncthreads();
            As[akv*4+0][ar]=av.x; As[akv*4+1][ar]=av.y;
            As[akv*4+2][ar]=av.z; As[akv*4+3][ar]=av.w;
            *(float4*)&Bs[brow][bc4 * 4] = bcur;
            __syncthreads();
            if (k0 + 16 < 512) {
                a1 = *(const float4*)(Wr_img + aoff + k0 + 16);
                a2 = *(const float4*)(Wr_txt + aoff + k0 + 16);
                bv = *(const float4*)(Bp + (size_t)(k0 + 16) * 1024);
            }
            #pragma unroll
            for (int k = 0; k < 16; k++) {
                float4 a = *(const float4*)&As[k][tm * 4];
                float4 b = *(const float4*)&Bs[k][tn * 4];
                acc[0][0]+=a.x*b.x; acc[0][1]+=a.x*b.y; acc[0][2]+=a.x*b.z; acc[0][3]+=a.x*b.w;
                acc[1][0]+=a.y*b.x; acc[1][1]+=a.y*b.y; acc[1][2]+=a.y*b.z; acc[1][3]+=a.y*b.w;
                acc[2][0]+=a.z*b.x; acc[2][1]+=a.z*b.y; acc[2][2]+=a.z*b.z; acc[2][3]+=a.z*b.w;
                acc[3][0]+=a.w*b.x; acc[3][1]+=a.w*b.y; acc[3][2]+=a.w*b.z; acc[3][3]+=a.w*b.w;
            }
        }
        const int row = bm * 64 + tm * 4;
        const int col = bn * 64 + tn * 4;
        #pragma unroll
        for (int i = 0; i < 4; i++)
            *(float4*)&g_Wbig[(size_t)(row + i) * KF + 1024 + col] =
                make_float4(acc[i][0], acc[i][1], acc[i][2], acc[i][3]);
        return;
    }
    bid -= 128;

    if (bid < 512) {   // ---- bc
        const int h = bid;
        float s = 0.0f;
        #pragma unroll
        for (int j = 0; j < 2; j++) {
            int k = tid + j * 256;
            s += (Wr_img[(size_t)h * 512 + k] + Wr_txt[(size_t)h * 512 + k]) * b_user[k];
        }
        #pragma unroll
        for (int o = 16; o; o >>= 1) s += __shfl_down_sync(0xffffffffu, s, o);
        if ((tid & 31) == 0) red8[tid >> 5] = s;
        __syncthreads();
        if (tid == 0) {
            float t = 0.f;
            #pragma unroll
            for (int i = 0; i < 8; i++) t += red8[i];
            g_bc[h] = t + bl_img[h] + bl_txt[h];
        }
        return;
    }
    bid -= 512;

    if (bid < 256) {   // ---- prep: Wbig[:,0:1024) = [Wl_img | Wl_txt]
        #pragma unroll
        for (int j = 0; j < 2; j++) {
            int q = bid * 256 + tid + j * 65536;
            int h = q >> 8, c4 = q & 255;
            int c = c4 * 4;
            float4 v = (c < 512)
                ? *(const float4*)(Wl_img + (size_t)h * 512 + c)
                : *(const float4*)(Wl_txt + (size_t)h * 512 + (c - 512));
            *(float4*)&g_Wbig[(size_t)h * KF + c] = v;
        }
        return;
    }
    bid -= 256;

    {   // ---- means (2048 blocks; proven 86% DRAM structure)
        const int b = bid;
        const int h4 = tid & 127;
        const bool isimg = (tid < 128);
        const float* src = isimg ? img : txt;
        const float4* base = (const float4*)(src + (size_t)b * MND * H_) + h4;

        float4 acc = make_float4(0.f, 0.f, 0.f, 0.f);
        #pragma unroll 16
        for (int m = 0; m < MND; m++) {
            float4 v = base[(size_t)m * (H_ / 4)];
            acc.x += v.x; acc.y += v.y; acc.z += v.z; acc.w += v.w;
        }
        const float inv = 1.0f / (float)MND;
        acc.x *= inv; acc.y *= inv; acc.z *= inv; acc.w *= inv;

        float4* xrow = (float4*)(g_X + (size_t)b * KF);
        xrow[(isimg ? 0 : 128) + h4] = acc;

        const float4* cs = (const float4*)((isimg ? it : ii) + (size_t)b * D_);
        xrow[(isimg ? 256 : 384) + h4] = cs[h4];
    }
}

// ===========================================================================
// Launch 2: split-K x4 FFMA GEMM. Grid (8,32,4) = 1024 units of 64x64x512
// -> 6.92 units/SM, quantization waste ~1% (vs 15.6% at 256 CTAs).
// Proven 4x4 inner loop + register prefetch; partials to 4 disjoint buffers.
// ===========================================================================
__global__ __launch_bounds__(256) void gemm_part() {
    __shared__ float As[16][68];
    __shared__ float Bs[16][68];
    const int bn = blockIdx.x;
    const int bm = blockIdx.y;
    const int kh = blockIdx.z;
    const int tid = threadIdx.x;
    const int tn = tid & 15, tm = tid >> 4;
    const int ar = tid >> 2, akv = tid & 3;

    const int kb = kh * KSEG;
    const float* Ap = g_X    + (size_t)(bm * 64 + ar) * KF + kb + akv * 4;
    const float* Bp = g_Wbig + (size_t)(bn * 64 + ar) * KF + kb + akv * 4;

    float acc[4][4] = {};
    float4 av = *(const float4*)(Ap);
    float4 bv = *(const float4*)(Bp);
    for (int k0 = 0; k0 < KSEG; k0 += 16) {
        float4 acur = av, bcur = bv;
        __syncthreads();
        As[akv*4+0][ar]=acur.x; As[akv*4+1][ar]=acur.y;
        As[akv*4+2][ar]=acur.z; As[akv*4+3][ar]=acur.w;
        Bs[akv*4+0][ar]=bcur.x; Bs[akv*4+1][ar]=bcur.y;
        Bs[akv*4+2][ar]=bcur.z; Bs[akv*4+3][ar]=bcur.w;
        __syncthreads();
        if (k0 + 16 < KSEG) {
            av = *(const float4*)(Ap + k0 + 16);
            bv = *(const float4*)(Bp + k0 + 16);
        }
        #pragma unroll
        for (int k = 0; k < 16; k++) {
            float4 a = *(const float4*)&As[k][tm * 4];
            float4 b = *(const float4*)&Bs[k][tn * 4];
            acc[0][0]+=a.x*b.x; acc[0][1]+=a.x*b.y; acc[0][2]+=a.x*b.z; acc[0][3]+=a.x*b.w;
            acc[1][0]+=a.y*b.x; acc[1][1]+=a.y*b.y; acc[1][2]+=a.y*b.z; acc[1][3]+=a.y*b.w;
            acc[2][0]+=a.z*b.x; acc[2][1]+=a.z*b.y; acc[2][2]+=a.z*b.z; acc[2][3]+=a.z*b.w;
            acc[3][0]+=a.w*b.x; acc[3][1]+=a.w*b.y; acc[3][2]+=a.w*b.z; acc[3][3]+=a.w*b.w;
        }
    }

    float* P = g_part[kh];
    const int row = bm * 64 + tm * 4;
    const int col = bn * 64 + tn * 4;
    #pragma unroll
    for (int i = 0; i < 4; i++)
        *(float4*)&P[(size_t)(row + i) * H_ + col] =
            make_float4(acc[i][0], acc[i][1], acc[i][2], acc[i][3]);
}

// ===========================================================================
// Launch 3: out = relu(p0+p1+p2+p3 + bc)   (~36MB traffic, ~4-5us)
// ===========================================================================
__global__ void epi_kernel(float* __restrict__ out) {
    int b = blockIdx.x * 2 + (threadIdx.x >> 7);
    int c4 = threadIdx.x & 127;
    size_t o = (size_t)b * H_ + c4 * 4;
    float4 s0 = *(const float4*)&g_part[0][o];
    float4 s1 = *(const float4*)&g_part[1][o];
    float4 s2 = *(const float4*)&g_part[2][o];
    float4 s3 = *(const float4*)&g_part[3][o];
    float4 bias = *(const float4*)&g_bc[c4 * 4];
    float4 v;
    v.x = fmaxf(s0.x + s1.x + s2.x + s3.x + bias.x, 0.f);
    v.y = fmaxf(s0.y + s1.y + s2.y + s3.y + bias.y, 0.f);
    v.z = fmaxf(s0.z + s1.z + s2.z + s3.z + bias.z, 0.f);
    v.w = fmaxf(s0.w + s1.w + s2.w + s3.w + bias.w, 0.f);
    *(float4*)&out[o] = v;
}

// ---------------------------------------------------------------------------
extern "C" void kernel_launch(void* const* d_in, const int* in_sizes, int n_in,
                              void* d_out, int out_size) {
    const float* it      = (const float*)d_in[0];
    const float* ii      = (const float*)d_in[1];
    const float* txt     = (const float*)d_in[2];
    const float* img     = (const float*)d_in[3];
    const float* W_user  = (const float*)d_in[4];
    const float* b_user  = (const float*)d_in[5];
    const float* Wl_img  = (const float*)d_in[6];
    const float* bl_img  = (const float*)d_in[7];
    const float* Wr_img  = (const float*)d_in[8];
    const float* Wl_txt  = (const float*)d_in[9];
    const float* bl_txt  = (const float*)d_in[10];
    const float* Wr_txt  = (const float*)d_in[11];
    float* out = (float*)d_out;

    // Launch 1: means + weight setup fused
    fused_means_setup<<<2944, 256>>>(img, txt, it, ii, Wl_img, Wl_txt,
                                     Wr_img, Wr_txt, W_user, b_user,
                                     bl_img, bl_txt);

    // Launch 2: split-K FFMA GEMM (1024 units -> ~1% tail waste)
    {
        dim3 grid(H_ / 64, B_ / 64, NKH);
        gemm_part<<<grid, 256>>>();
    }

    // Launch 3: reduce partials + bias + ReLU
    epi_kernel<<<B_ / 2, 256>>>(out);
}